// round 11
// baseline (speedup 1.0000x reference)
#include <cuda_runtime.h>
#include <cuda_bf16.h>
#include <cstdint>

#define NIMG 16
#define NBOX 16128
#define NCH  85
#define KSEL 500
#define KPAD 512
#define NCB  16            // 512 / 32 column blocks
#define SIG_NEG4 0.017986210f   // sigmoid(-4) for zero-overlap pairs

// ---------------- device scratch (no allocations allowed) ----------------
__device__ unsigned g_sbits[NIMG * NBOX];                 // packed score bits
__device__ float    g_s[NIMG][KPAD];                      // sorted top scores
__device__ float4   g_box[NIMG][KPAD];                    // gathered boxes
__device__ float    g_y[NIMG][KPAD];                      // gathered targets
__device__ float    g_pT[NIMG][NCB][32][KPAD];            // prune TRANSPOSED [img][cb][t][row]
__device__ float    g_tri[NIMG][NCB][4][32];              // packed diag 8x8 sub-triangles
__device__ float    g_loss[NIMG];                         // per-image 1-AP

__constant__ unsigned char c_tk[28] = {1,2,2,3,3,3,4,4,4,4,5,5,5,5,5,
                                       6,6,6,6,6,6,7,7,7,7,7,7,7};
__constant__ unsigned char c_tj[28] = {0,0,1,0,1,2,0,1,2,3,0,1,2,3,4,
                                       0,1,2,3,4,5,0,1,2,3,4,5,6};

__device__ __forceinline__ float frcp(float x) {
    float r; asm("rcp.approx.f32 %0, %1;" : "=f"(r) : "f"(x)); return r;
}

// ---------------- K1: scores = max over channels 1..84 ----------------
__global__ __launch_bounds__(128) void k_scores(const float* __restrict__ preds) {
    __shared__ __align__(16) float sh[128 * NCH];
    int img = blockIdx.x / 126;
    int ch  = blockIdx.x % 126;
    size_t base = ((size_t)img * NBOX + (size_t)ch * 128) * NCH;
    const float4* src = reinterpret_cast<const float4*>(preds + base);
    float4* dst = reinterpret_cast<float4*>(sh);
    #pragma unroll 8
    for (int u = threadIdx.x; u < 128 * NCH / 4; u += 128) dst[u] = src[u];
    __syncthreads();
    int r = threadIdx.x;
    float m = sh[r * NCH + 1];
    #pragma unroll
    for (int c = 2; c < NCH; ++c) m = fmaxf(m, sh[r * NCH + c]);
    g_sbits[(size_t)img * NBOX + ch * 128 + r] = __float_as_uint(m);
}

// ---------------- K2: per-image radix select (4x8-bit) + bitonic ----------------
__global__ __launch_bounds__(512) void k_select(const float4* __restrict__ boxes,
                                                const int* __restrict__ tgt) {
    const int img = blockIdx.x;
    const int tid = threadIdx.x;
    const int w = tid >> 5, lane = tid & 31;
    __shared__ unsigned whist[16 * 256];
    __shared__ unsigned hist[256];
    __shared__ unsigned wtot[16];
    __shared__ unsigned s_bin, s_rem, s_cnt;
    __shared__ unsigned long long sbuf[1024];
    const unsigned* sb = g_sbits + (size_t)img * NBOX;

    unsigned prefix = 0;
    unsigned target = KSEL;

    #pragma unroll
    for (int pass = 0; pass < 4; ++pass) {
        const int shift = 24 - pass * 8;
        for (int u = tid; u < 4096; u += 512) whist[u] = 0;
        __syncthreads();
        for (int j = tid; j < NBOX; j += 512) {
            unsigned bits = sb[j];
            bool ok = (pass == 0) || ((bits >> (shift + 8)) == prefix);
            unsigned act = __ballot_sync(0xFFFFFFFFu, ok);
            if (ok) {
                unsigned bin = (bits >> shift) & 255u;
                unsigned mask = __match_any_sync(act, bin);
                if ((mask & ((1u << lane) - 1u)) == 0)
                    whist[w * 256 + bin] += __popc(mask);
            }
        }
        __syncthreads();
        if (tid < 256) {
            unsigned h = 0;
            #pragma unroll
            for (int ww = 0; ww < 16; ++ww) h += whist[ww * 256 + tid];
            hist[tid] = h;
        }
        __syncthreads();
        unsigned x0 = (tid < 256) ? hist[255 - tid] : 0u;
        unsigned x = x0;
        #pragma unroll
        for (int off = 1; off < 32; off <<= 1) {
            unsigned yv = __shfl_up_sync(0xFFFFFFFFu, x, off);
            if (lane >= off) x += yv;
        }
        if (lane == 31) wtot[w] = x;
        __syncthreads();
        unsigned add = 0;
        #pragma unroll
        for (int ww = 0; ww < 8; ++ww) if (ww < w) add += wtot[ww];
        unsigned inc = x + add;
        if (tid < 256 && inc >= target && (inc - x0) < target) {
            s_bin = 255u - (unsigned)tid;
            s_rem = target - (inc - x0);
        }
        __syncthreads();
        prefix = (prefix << 8) | s_bin;
        target = s_rem;
        __syncthreads();
    }
    const unsigned T = prefix;

    for (int u = tid; u < 1024; u += 512) sbuf[u] = ~0ULL;
    if (tid == 0) s_cnt = 0;
    __syncthreads();
    for (int j = tid; j < NBOX; j += 512) {
        unsigned bits = sb[j];
        if (bits >= T) {
            unsigned p = atomicAdd(&s_cnt, 1);
            if (p < 1024)
                sbuf[p] = ~(((unsigned long long)bits << 32) |
                            (unsigned long long)(0xFFFFFFFFu - (unsigned)j));
        }
    }
    __syncthreads();

    for (unsigned kk = 2; kk <= 1024; kk <<= 1) {
        for (unsigned st = kk >> 1; st > 0; st >>= 1) {
            unsigned t = (unsigned)tid;
            unsigned i = ((t & ~(st - 1)) << 1) | (t & (st - 1));
            unsigned j2 = i | st;
            bool up = ((i & kk) == 0);
            unsigned long long a = sbuf[i], b = sbuf[j2];
            if ((a > b) == up) { sbuf[i] = b; sbuf[j2] = a; }
            __syncthreads();
        }
    }

    if (tid < KSEL) {
        unsigned long long key = ~sbuf[tid];
        unsigned bits = (unsigned)(key >> 32);
        unsigned idx  = 0xFFFFFFFFu - (unsigned)(key & 0xFFFFFFFFull);
        g_s[img][tid] = __uint_as_float(bits);
        g_box[img][tid] = boxes[(size_t)img * NBOX + idx];
        g_y[img][tid] = (float)tgt[(size_t)img * NBOX + idx];
    } else {
        g_s[img][tid] = 0.f;
        g_box[img][tid] = make_float4(0.f, 0.f, 0.f, 0.f);
        g_y[img][tid] = 0.f;
    }
}

// ---------------- K3: prune matrix (transposed) + packed diag triangles ----------------
// grid (34, NIMG) x 128: 4 warps/block, one 32x32 tile per warp, 136 tiles/img.
__global__ __launch_bounds__(128) void k_prune() {
    const int img = blockIdx.y;
    const int w = threadIdx.x >> 5, lane = threadIdx.x & 31;
    const int t = blockIdx.x * 4 + w;                 // tile id, 0..135
    __shared__ float4 sbj[4][32];
    __shared__ float  saj[4][32];
    __shared__ float  sdiag[4][32][32];

    int rb = (int)((sqrtf(8.f * (float)t + 1.f) - 1.f) * 0.5f);
    if ((rb + 1) * (rb + 2) / 2 <= t) rb++;
    if (rb * (rb + 1) / 2 > t) rb--;
    const int cb = t - rb * (rb + 1) / 2;

    {
        float4 b = g_box[img][cb * 32 + lane];
        sbj[w][lane] = b;
        saj[w][lane] = fmaxf(b.z - b.x, 0.f) * fmaxf(b.w - b.y, 0.f);
    }
    __syncwarp();

    const int i = rb * 32 + lane;
    float4 bi = g_box[img][i];
    float ai = fmaxf(bi.z - bi.x, 0.f) * fmaxf(bi.w - bi.y, 0.f);
    float out[32];
    #pragma unroll
    for (int c = 0; c < 32; ++c) {
        float4 bb = sbj[w][c];
        float iw = fminf(bi.z, bb.z) - fmaxf(bi.x, bb.x);
        float ih = fminf(bi.w, bb.w) - fmaxf(bi.y, bb.y);
        bool ov = (iw > 0.f) && (ih > 0.f);
        float p;
        if (__any_sync(0xFFFFFFFFu, ov)) {
            float inter = fmaxf(iw, 0.f) * fmaxf(ih, 0.f);
            float uni = ai + saj[w][c] - inter;
            float iou = inter * frcp(fmaxf(uni, 1e-9f));
            p = frcp(1.f + __expf((0.4f - iou) * 10.f));
        } else {
            p = SIG_NEG4;
        }
        out[c] = p;
        g_pT[img][cb][c][i] = p;      // transposed: coalesced across lanes
    }

    // diag tiles: extract packed 8x8 sub-block triangles for k_nms
    if (rb == cb) {
        #pragma unroll
        for (int c = 0; c < 32; ++c) sdiag[w][lane][c] = out[c];
        __syncwarp();
        for (int e = lane; e < 112; e += 32) {
            int q = e / 28, rem = e - q * 28;
            int k = c_tk[rem], j = c_tj[rem];
            g_tri[img][cb][q][rem] = sdiag[w][q * 8 + k][q * 8 + j];
        }
    }
}

// ---------------- K4: soft-NMS + fused ap_loss ----------------
__global__ __launch_bounds__(512) void k_nms() {
    const int img = blockIdx.x;
    const int tid = threadIdx.x;
    const int w = tid >> 5, lane = tid & 31;
    __shared__ __align__(16) float vsh[KPAD];
    __shared__ float tri[NCB][4][32];
    __shared__ float Esh[KPAD];
    __shared__ __align__(16) float4 prs[KPAD / 2];
    __shared__ int   rowss[KPAD];
    __shared__ int   wcnt[NCB];
    __shared__ float wprec[NCB];
    const float* pT = &g_pT[img][0][0][0];       // [cb][t][row], row stride KPAD

    // stage packed triangles (2KB, coalesced)
    for (int u = tid; u < NCB * 4 * 32; u += 512)
        reinterpret_cast<float*>(tri)[u] =
            reinterpret_cast<const float*>(g_tri)[img * (NCB * 4 * 32) + u];

    float cur[32], nxt[32];
    #pragma unroll
    for (int u = 0; u < 32; ++u) cur[u] = pT[u * KPAD + tid];   // tile 0, coalesced

    float rr = g_s[img][tid];
    __syncthreads();                              // tri visible

    for (int cb = 0; cb < NCB; ++cb) {
        if (cb < NCB - 1 && w >= cb + 1) {        // prefetch next tile (coalesced)
            const float* nb = pT + (size_t)(cb + 1) * 32 * KPAD;
            #pragma unroll
            for (int u = 0; u < 32; ++u) nxt[u] = nb[u * KPAD + tid];
        }
        if (w == cb) {
            // 8-col speculative sub-blocks (R3-verified numerics)
            #pragma unroll
            for (int q = 0; q < 4; ++q) {
                const int base = q * 8;
                const float* tq = &tri[cb][q][0];
                float a0 = __shfl_sync(0xFFFFFFFFu, rr, base + 0);
                float a1 = __shfl_sync(0xFFFFFFFFu, rr, base + 1);
                float a2 = __shfl_sync(0xFFFFFFFFu, rr, base + 2);
                float a3 = __shfl_sync(0xFFFFFFFFu, rr, base + 3);
                float a4 = __shfl_sync(0xFFFFFFFFu, rr, base + 4);
                float a5 = __shfl_sync(0xFFFFFFFFu, rr, base + 5);
                float a6 = __shfl_sync(0xFFFFFFFFu, rr, base + 6);
                float a7 = __shfl_sync(0xFFFFFFFFu, rr, base + 7);
                float v0 = fmaxf(a0, 0.f);
                a1 = fmaf(-tq[0], v0, a1);  float v1 = fmaxf(a1, 0.f);
                a2 = fmaf(-tq[1], v0, a2);  a2 = fmaf(-tq[2], v1, a2);
                float v2 = fmaxf(a2, 0.f);
                a3 = fmaf(-tq[3], v0, a3);  a3 = fmaf(-tq[4], v1, a3);
                a3 = fmaf(-tq[5], v2, a3);  float v3 = fmaxf(a3, 0.f);
                a4 = fmaf(-tq[6], v0, a4);  a4 = fmaf(-tq[7], v1, a4);
                a4 = fmaf(-tq[8], v2, a4);  a4 = fmaf(-tq[9], v3, a4);
                float v4 = fmaxf(a4, 0.f);
                a5 = fmaf(-tq[10], v0, a5); a5 = fmaf(-tq[11], v1, a5);
                a5 = fmaf(-tq[12], v2, a5); a5 = fmaf(-tq[13], v3, a5);
                a5 = fmaf(-tq[14], v4, a5); float v5 = fmaxf(a5, 0.f);
                a6 = fmaf(-tq[15], v0, a6); a6 = fmaf(-tq[16], v1, a6);
                a6 = fmaf(-tq[17], v2, a6); a6 = fmaf(-tq[18], v3, a6);
                a6 = fmaf(-tq[19], v4, a6); a6 = fmaf(-tq[20], v5, a6);
                float v6 = fmaxf(a6, 0.f);
                a7 = fmaf(-tq[21], v0, a7); a7 = fmaf(-tq[22], v1, a7);
                a7 = fmaf(-tq[23], v2, a7); a7 = fmaf(-tq[24], v3, a7);
                a7 = fmaf(-tq[25], v4, a7); a7 = fmaf(-tq[26], v5, a7);
                a7 = fmaf(-tq[27], v6, a7); float v7 = fmaxf(a7, 0.f);
                if (lane == base + 0) vsh[tid] = v0;
                if (lane == base + 1) vsh[tid] = v1;
                if (lane == base + 2) vsh[tid] = v2;
                if (lane == base + 3) vsh[tid] = v3;
                if (lane == base + 4) vsh[tid] = v4;
                if (lane == base + 5) vsh[tid] = v5;
                if (lane == base + 6) vsh[tid] = v6;
                if (lane == base + 7) vsh[tid] = v7;
                float m01 = cur[base + 0] * v0; m01 = fmaf(cur[base + 1], v1, m01);
                float m23 = cur[base + 2] * v2; m23 = fmaf(cur[base + 3], v3, m23);
                float m45 = cur[base + 4] * v4; m45 = fmaf(cur[base + 5], v5, m45);
                float m67 = cur[base + 6] * v6; m67 = fmaf(cur[base + 7], v7, m67);
                rr = rr - ((m01 + m23) + (m45 + m67));
            }
        }
        __syncthreads();
        if (w > cb) {
            const float4* vv = reinterpret_cast<const float4*>(&vsh[cb * 32]);
            float s0 = 0.f, s1 = 0.f, s2 = 0.f, s3 = 0.f;
            #pragma unroll
            for (int u = 0; u < 8; ++u) {
                float4 v4 = vv[u];
                s0 = fmaf(cur[4*u+0], v4.x, s0);
                s1 = fmaf(cur[4*u+1], v4.y, s1);
                s2 = fmaf(cur[4*u+2], v4.z, s2);
                s3 = fmaf(cur[4*u+3], v4.w, s3);
            }
            rr = rr - ((s0 + s1) + (s2 + s3));
        }
        #pragma unroll
        for (int u = 0; u < 32; ++u) cur[u] = nxt[u];
    }
    __syncthreads();

    // ---- epilogue: E, pair constants, compaction (all in shared) ----
    float v = vsh[tid];
    bool valid = tid < KSEL;
    float E = valid ? __expf(20.f * v) : 0.f;
    float y = valid ? g_y[img][tid] : 0.f;
    Esh[tid] = E;

    float Eb = __shfl_down_sync(0xFFFFFFFFu, E, 1);
    float yb = __shfl_down_sync(0xFFFFFFFFu, y, 1);
    if (!(lane & 1)) {
        float S = E + Eb;
        float P = E * Eb;
        float yS = fmaf(y, E, yb * Eb);
        float yP = (y + yb) * P;
        prs[tid >> 1] = make_float4(S, P, yS, yP);
    }

    bool pos = valid && (y != 0.f);
    unsigned vote = __ballot_sync(0xFFFFFFFFu, pos);
    if (lane == 0) wcnt[w] = __popc(vote);
    __syncthreads();                              // Esh, prs, wcnt visible
    int base2 = 0, npos = 0;
    #pragma unroll
    for (int ww = 0; ww < NCB; ++ww) {
        int c = wcnt[ww];
        if (ww < w) base2 += c;
        npos += c;
    }
    if (pos) {
        int off = __popc(vote & ((1u << lane) - 1u));
        rowss[base2 + off] = tid;
    }
    __syncthreads();                              // rowss visible

    // ---- fused ap_loss: one warp per positive row ----
    // h_ia + h_ib = (Ei*S + 2P) / (Ei^2 + Ei*S + P)
    float accp = 0.f;
    for (int slot = w; slot < npos; slot += NCB) {
        const int i = rowss[slot];
        const float Ei = Esh[i];
        float sh = 0.f, shy = 0.f;
        #pragma unroll
        for (int u = 0; u < 8; ++u) {
            float4 q = prs[u * 32 + lane];
            float t = fmaf(Ei, q.x, q.y);
            float num = t + q.y;
            float den = fmaf(Ei, Ei, t);
            float r2 = frcp(den);
            sh = fmaf(num, r2, sh);
            float numy = fmaf(Ei, q.z, q.w);
            shy = fmaf(numy, r2, shy);
        }
        #pragma unroll
        for (int off = 16; off > 0; off >>= 1) {
            sh  += __shfl_down_sync(0xFFFFFFFFu, sh, off);
            shy += __shfl_down_sync(0xFFFFFFFFu, shy, off);
        }
        if (lane == 0) accp += __fdividef(0.5f + shy, 0.5f + sh);
    }
    if (lane == 0) wprec[w] = accp;
    __syncthreads();
    if (tid == 0) {
        float tot = 0.f;
        #pragma unroll
        for (int ww = 0; ww < NCB; ++ww) tot += wprec[ww];
        g_loss[img] = 1.f - tot / fmaxf((float)npos, 1.f);
    }
}

// ---------------- K5: final mean over images ----------------
__global__ __launch_bounds__(32) void k_final(float* __restrict__ out) {
    if (threadIdx.x == 0) {
        float t = 0.f;
        #pragma unroll
        for (int k = 0; k < NIMG; ++k) t += g_loss[k];
        out[0] = t / (float)NIMG;
    }
}

// ---------------- driver ----------------
extern "C" void kernel_launch(void* const* d_in, const int* in_sizes, int n_in,
                              void* d_out, int out_size) {
    const float* preds = nullptr;
    const float* boxes = nullptr;
    const int*   targets = nullptr;
    for (int i = 0; i < n_in; ++i) {
        long sz = in_sizes[i];
        if (sz == (long)NIMG * NBOX * NCH) preds = (const float*)d_in[i];
        else if (sz == (long)NIMG * NBOX * 4) boxes = (const float*)d_in[i];
        else if (sz == (long)NIMG * NBOX) targets = (const int*)d_in[i];
    }
    if (!preds)   preds   = (const float*)d_in[0];
    if (!boxes)   boxes   = (const float*)d_in[1];
    if (!targets) targets = (const int*)d_in[2];

    k_scores<<<NIMG * 126, 128>>>(preds);
    k_select<<<NIMG, 512>>>(reinterpret_cast<const float4*>(boxes), targets);
    k_prune<<<dim3(34, NIMG), 128>>>();
    k_nms<<<NIMG, 512>>>();
    k_final<<<1, 32>>>((float*)d_out);
}

// round 12
// speedup vs baseline: 1.3701x; 1.3701x over previous
#include <cuda_runtime.h>
#include <cuda_bf16.h>
#include <cstdint>

#define NIMG 16
#define NBOX 16128
#define NCH  85
#define KSEL 500
#define KPAD 512
#define NCB  16            // 512 / 32 column blocks
#define SIG_NEG4 0.017986210f   // sigmoid(-4) for zero-overlap pairs

// ---------------- device scratch (no allocations allowed) ----------------
__device__ unsigned g_sbits[NIMG * NBOX];                 // packed score bits
__device__ float    g_s[NIMG][KPAD];                      // sorted top scores
__device__ float4   g_box[NIMG][KPAD];                    // gathered boxes
__device__ float    g_y[NIMG][KPAD];                      // gathered targets
__device__ float    g_pT[NIMG][NCB][32][KPAD];            // prune TRANSPOSED [img][cb][t][row]
__device__ float    g_loss[NIMG];                         // per-image 1-AP

__device__ __forceinline__ float frcp(float x) {
    float r; asm("rcp.approx.f32 %0, %1;" : "=f"(r) : "f"(x)); return r;
}

// ---------------- K1: scores = max over channels 1..84 ----------------
__global__ __launch_bounds__(128) void k_scores(const float* __restrict__ preds) {
    __shared__ __align__(16) float sh[128 * NCH];
    int img = blockIdx.x / 126;
    int ch  = blockIdx.x % 126;
    size_t base = ((size_t)img * NBOX + (size_t)ch * 128) * NCH;
    const float4* src = reinterpret_cast<const float4*>(preds + base);
    float4* dst = reinterpret_cast<float4*>(sh);
    #pragma unroll 8
    for (int u = threadIdx.x; u < 128 * NCH / 4; u += 128) dst[u] = src[u];
    __syncthreads();
    int r = threadIdx.x;
    float m = sh[r * NCH + 1];
    #pragma unroll
    for (int c = 2; c < NCH; ++c) m = fmaxf(m, sh[r * NCH + c]);
    g_sbits[(size_t)img * NBOX + ch * 128 + r] = __float_as_uint(m);
}

// ---------------- K2: per-image radix select (4x8-bit) + bitonic ----------------
__global__ __launch_bounds__(512) void k_select(const float4* __restrict__ boxes,
                                                const int* __restrict__ tgt) {
    const int img = blockIdx.x;
    const int tid = threadIdx.x;
    const int w = tid >> 5, lane = tid & 31;
    __shared__ unsigned whist[16 * 256];
    __shared__ unsigned hist[256];
    __shared__ unsigned wtot[16];
    __shared__ unsigned s_bin, s_rem, s_cnt;
    __shared__ unsigned long long sbuf[1024];
    const unsigned* sb = g_sbits + (size_t)img * NBOX;

    unsigned prefix = 0;
    unsigned target = KSEL;

    #pragma unroll
    for (int pass = 0; pass < 4; ++pass) {
        const int shift = 24 - pass * 8;
        for (int u = tid; u < 4096; u += 512) whist[u] = 0;
        __syncthreads();
        for (int j = tid; j < NBOX; j += 512) {
            unsigned bits = sb[j];
            bool ok = (pass == 0) || ((bits >> (shift + 8)) == prefix);
            unsigned act = __ballot_sync(0xFFFFFFFFu, ok);
            if (ok) {
                unsigned bin = (bits >> shift) & 255u;
                unsigned mask = __match_any_sync(act, bin);
                if ((mask & ((1u << lane) - 1u)) == 0)
                    whist[w * 256 + bin] += __popc(mask);
            }
        }
        __syncthreads();
        if (tid < 256) {
            unsigned h = 0;
            #pragma unroll
            for (int ww = 0; ww < 16; ++ww) h += whist[ww * 256 + tid];
            hist[tid] = h;
        }
        __syncthreads();
        unsigned x0 = (tid < 256) ? hist[255 - tid] : 0u;
        unsigned x = x0;
        #pragma unroll
        for (int off = 1; off < 32; off <<= 1) {
            unsigned yv = __shfl_up_sync(0xFFFFFFFFu, x, off);
            if (lane >= off) x += yv;
        }
        if (lane == 31) wtot[w] = x;
        __syncthreads();
        unsigned add = 0;
        #pragma unroll
        for (int ww = 0; ww < 8; ++ww) if (ww < w) add += wtot[ww];
        unsigned inc = x + add;
        if (tid < 256 && inc >= target && (inc - x0) < target) {
            s_bin = 255u - (unsigned)tid;
            s_rem = target - (inc - x0);
        }
        __syncthreads();
        prefix = (prefix << 8) | s_bin;
        target = s_rem;
        __syncthreads();
    }
    const unsigned T = prefix;

    for (int u = tid; u < 1024; u += 512) sbuf[u] = ~0ULL;
    if (tid == 0) s_cnt = 0;
    __syncthreads();
    for (int j = tid; j < NBOX; j += 512) {
        unsigned bits = sb[j];
        if (bits >= T) {
            unsigned p = atomicAdd(&s_cnt, 1);
            if (p < 1024)
                sbuf[p] = ~(((unsigned long long)bits << 32) |
                            (unsigned long long)(0xFFFFFFFFu - (unsigned)j));
        }
    }
    __syncthreads();

    for (unsigned kk = 2; kk <= 1024; kk <<= 1) {
        for (unsigned st = kk >> 1; st > 0; st >>= 1) {
            unsigned t = (unsigned)tid;
            unsigned i = ((t & ~(st - 1)) << 1) | (t & (st - 1));
            unsigned j2 = i | st;
            bool up = ((i & kk) == 0);
            unsigned long long a = sbuf[i], b = sbuf[j2];
            if ((a > b) == up) { sbuf[i] = b; sbuf[j2] = a; }
            __syncthreads();
        }
    }

    if (tid < KSEL) {
        unsigned long long key = ~sbuf[tid];
        unsigned bits = (unsigned)(key >> 32);
        unsigned idx  = 0xFFFFFFFFu - (unsigned)(key & 0xFFFFFFFFull);
        g_s[img][tid] = __uint_as_float(bits);
        g_box[img][tid] = boxes[(size_t)img * NBOX + idx];
        g_y[img][tid] = (float)tgt[(size_t)img * NBOX + idx];
    } else {
        g_s[img][tid] = 0.f;
        g_box[img][tid] = make_float4(0.f, 0.f, 0.f, 0.f);
        g_y[img][tid] = 0.f;
    }
}

// ---------------- K3: prune matrix, triangle tiles only, TRANSPOSED store ----------------
// grid (34, NIMG) x 128: 4 warps/block, one 32x32 tile per warp, 136 tiles/img.
__global__ __launch_bounds__(128) void k_prune() {
    const int img = blockIdx.y;
    const int w = threadIdx.x >> 5, lane = threadIdx.x & 31;
    const int t = blockIdx.x * 4 + w;                 // tile id, 0..135
    __shared__ float4 sbj[4][32];
    __shared__ float  saj[4][32];

    int rb = (int)((sqrtf(8.f * (float)t + 1.f) - 1.f) * 0.5f);
    if ((rb + 1) * (rb + 2) / 2 <= t) rb++;
    if (rb * (rb + 1) / 2 > t) rb--;
    const int cb = t - rb * (rb + 1) / 2;

    {
        float4 b = g_box[img][cb * 32 + lane];
        sbj[w][lane] = b;
        saj[w][lane] = fmaxf(b.z - b.x, 0.f) * fmaxf(b.w - b.y, 0.f);
    }
    __syncwarp();

    const int i = rb * 32 + lane;
    float4 bi = g_box[img][i];
    float ai = fmaxf(bi.z - bi.x, 0.f) * fmaxf(bi.w - bi.y, 0.f);
    #pragma unroll
    for (int c = 0; c < 32; ++c) {
        float4 bb = sbj[w][c];
        float iw = fminf(bi.z, bb.z) - fmaxf(bi.x, bb.x);
        float ih = fminf(bi.w, bb.w) - fmaxf(bi.y, bb.y);
        bool ov = (iw > 0.f) && (ih > 0.f);
        float p;
        if (__any_sync(0xFFFFFFFFu, ov)) {
            float inter = fmaxf(iw, 0.f) * fmaxf(ih, 0.f);
            float uni = ai + saj[w][c] - inter;
            float iou = inter * frcp(fmaxf(uni, 1e-9f));
            p = frcp(1.f + __expf((0.4f - iou) * 10.f));
        } else {
            p = SIG_NEG4;
        }
        g_pT[img][cb][c][i] = p;      // transposed: coalesced across lanes
    }
}

// ---------------- K4: soft-NMS (R10 main loop, byte-identical) + fused ap ----------------
__global__ __launch_bounds__(512) void k_nms() {
    const int img = blockIdx.x;
    const int tid = threadIdx.x;
    const int w = tid >> 5, lane = tid & 31;
    __shared__ __align__(16) float vsh[KPAD];
    __shared__ float Esh[KPAD];
    __shared__ __align__(16) float4 prs[KPAD / 2];
    __shared__ int   rowss[KPAD];
    __shared__ int   wcnt[NCB];
    __shared__ float wprec[NCB];
    const float* pT = &g_pT[img][0][0][0];       // [cb][t][row], row stride KPAD

    float cur[32], nxt[32];
    #pragma unroll
    for (int u = 0; u < 32; ++u) cur[u] = pT[u * KPAD + tid];   // tile 0, coalesced

    float s = g_s[img][tid];
    float acc = 0.f;
    for (int cb = 0; cb < NCB; ++cb) {
        if (cb < NCB - 1 && w >= cb + 1) {       // prefetch next tile (coalesced scalar LDGs)
            const float* nb = pT + (size_t)(cb + 1) * 32 * KPAD;
            #pragma unroll
            for (int u = 0; u < 32; ++u) nxt[u] = nb[u * KPAD + tid];
        }
        if (w == cb) {
            // serial resolution of 32 diagonal columns via shfl chain
            float rr = s - acc;
            #pragma unroll
            for (int m = 0; m < 32; ++m) {
                float vm = __shfl_sync(0xFFFFFFFFu, fmaxf(rr, 0.f), m);
                if (lane == m) vsh[tid] = vm;
                if (lane > m) rr = fmaf(-cur[m], vm, rr);
            }
        }
        __syncthreads();
        if (w > cb) {
            const float4* vv = reinterpret_cast<const float4*>(&vsh[cb * 32]);
            #pragma unroll
            for (int u = 0; u < 8; ++u) {
                float4 v4 = vv[u];
                acc = fmaf(cur[4*u+0], v4.x, acc);
                acc = fmaf(cur[4*u+1], v4.y, acc);
                acc = fmaf(cur[4*u+2], v4.z, acc);
                acc = fmaf(cur[4*u+3], v4.w, acc);
            }
        }
        #pragma unroll
        for (int u = 0; u < 32; ++u) cur[u] = nxt[u];
    }
    __syncthreads();

    // ---- epilogue: E, pair constants, compaction (all in shared) ----
    float v = vsh[tid];
    bool valid = tid < KSEL;
    float E = valid ? __expf(20.f * v) : 0.f;
    float y = valid ? g_y[img][tid] : 0.f;
    Esh[tid] = E;

    float Eb = __shfl_down_sync(0xFFFFFFFFu, E, 1);
    float yb = __shfl_down_sync(0xFFFFFFFFu, y, 1);
    if (!(lane & 1)) {
        float S = E + Eb;
        float P = E * Eb;
        float yS = fmaf(y, E, yb * Eb);
        float yP = (y + yb) * P;
        prs[tid >> 1] = make_float4(S, P, yS, yP);
    }

    bool pos = valid && (y != 0.f);
    unsigned vote = __ballot_sync(0xFFFFFFFFu, pos);
    if (lane == 0) wcnt[w] = __popc(vote);
    __syncthreads();                              // Esh, prs, wcnt visible
    int base2 = 0, npos = 0;
    #pragma unroll
    for (int ww = 0; ww < NCB; ++ww) {
        int c = wcnt[ww];
        if (ww < w) base2 += c;
        npos += c;
    }
    if (pos) {
        int off = __popc(vote & ((1u << lane) - 1u));
        rowss[base2 + off] = tid;
    }
    __syncthreads();                              // rowss visible

    // ---- fused ap_loss: one warp per positive row ----
    // h_ia + h_ib = (Ei*S + 2P) / (Ei^2 + Ei*S + P)
    float accp = 0.f;
    for (int slot = w; slot < npos; slot += NCB) {
        const int i = rowss[slot];
        const float Ei = Esh[i];
        float sh = 0.f, shy = 0.f;
        #pragma unroll
        for (int u = 0; u < 8; ++u) {
            float4 q = prs[u * 32 + lane];
            float t = fmaf(Ei, q.x, q.y);
            float num = t + q.y;
            float den = fmaf(Ei, Ei, t);
            float r2 = frcp(den);
            sh = fmaf(num, r2, sh);
            float numy = fmaf(Ei, q.z, q.w);
            shy = fmaf(numy, r2, shy);
        }
        #pragma unroll
        for (int off = 16; off > 0; off >>= 1) {
            sh  += __shfl_down_sync(0xFFFFFFFFu, sh, off);
            shy += __shfl_down_sync(0xFFFFFFFFu, shy, off);
        }
        if (lane == 0) accp += __fdividef(0.5f + shy, 0.5f + sh);
    }
    if (lane == 0) wprec[w] = accp;
    __syncthreads();
    if (tid == 0) {
        float tot = 0.f;
        #pragma unroll
        for (int ww = 0; ww < NCB; ++ww) tot += wprec[ww];
        g_loss[img] = 1.f - tot / fmaxf((float)npos, 1.f);
    }
}

// ---------------- K5: final mean over images ----------------
__global__ __launch_bounds__(32) void k_final(float* __restrict__ out) {
    if (threadIdx.x == 0) {
        float t = 0.f;
        #pragma unroll
        for (int k = 0; k < NIMG; ++k) t += g_loss[k];
        out[0] = t / (float)NIMG;
    }
}

// ---------------- driver ----------------
extern "C" void kernel_launch(void* const* d_in, const int* in_sizes, int n_in,
                              void* d_out, int out_size) {
    const float* preds = nullptr;
    const float* boxes = nullptr;
    const int*   targets = nullptr;
    for (int i = 0; i < n_in; ++i) {
        long sz = in_sizes[i];
        if (sz == (long)NIMG * NBOX * NCH) preds = (const float*)d_in[i];
        else if (sz == (long)NIMG * NBOX * 4) boxes = (const float*)d_in[i];
        else if (sz == (long)NIMG * NBOX) targets = (const int*)d_in[i];
    }
    if (!preds)   preds   = (const float*)d_in[0];
    if (!boxes)   boxes   = (const float*)d_in[1];
    if (!targets) targets = (const int*)d_in[2];

    k_scores<<<NIMG * 126, 128>>>(preds);
    k_select<<<NIMG, 512>>>(reinterpret_cast<const float4*>(boxes), targets);
    k_prune<<<dim3(34, NIMG), 128>>>();
    k_nms<<<NIMG, 512>>>();
    k_final<<<1, 32>>>((float*)d_out);
}